// round 1
// baseline (speedup 1.0000x reference)
#include <cuda_runtime.h>

#define Bq 8
#define Nn 1024
#define Mw 64
#define Ee 63456
#define ROWS (Bq*Ee)   /* 507648, divisible by 64 */

// ---------------- device scratch (static, allowed) ----------------
__device__ float g_We[128*64];          // fused We1@We2
__device__ float g_Wn[192*64];          // fused Wn1@Wn2
__device__ float g_be[64];
__device__ float g_bn[64];
__device__ float g_Wcat[64*192];        // [We_edge | Wn_edge | W_e_edge]
__device__ float g_Pes[Bq*Nn*64];       // nodes @ We_src
__device__ float g_Pns[Bq*Nn*64];       // nodes @ Wn_src
__device__ float g_Pnd[Bq*Nn*64];       // nodes @ Wn_dst
__device__ float g_Qe[(size_t)ROWS*192];   // edge projections (3x64)
__device__ float g_mean[(size_t)ROWS*64];  // exclusive prefix mean of pair_e
__device__ float g_agg[Bq*Nn*64];       // agg_n

__device__ __forceinline__ int node_w(int i)      { return i < Mw ? i : Mw; }
__device__ __forceinline__ int node_start(int i)  { return i <= Mw ? (i*(i-1))/2 : 2016 + (i-Mw)*Mw; }

// ---------------- K0: fuse the two 2-layer (linear∘linear) MLPs ----------------
__global__ void k_fuse(const float* __restrict__ We1, const float* __restrict__ We2,
                       const float* __restrict__ be1, const float* __restrict__ be2,
                       const float* __restrict__ Wn1, const float* __restrict__ bn1,
                       const float* __restrict__ Wn2, const float* __restrict__ bn2) {
    int idx = blockIdx.x*blockDim.x + threadIdx.x;
    if (idx < 128*64) {
        int j = idx >> 6, c = idx & 63; float s = 0.f;
        for (int t = 0; t < 128; t++) s += We1[j*128+t]*We2[t*64+c];
        g_We[idx] = s;
    }
    int i2 = idx - 128*64;
    if (i2 >= 0 && i2 < 192*64) {
        int j = i2 >> 6, c = i2 & 63; float s = 0.f;
        for (int t = 0; t < 128; t++) s += Wn1[j*128+t]*Wn2[t*64+c];
        g_Wn[i2] = s;
    }
    int i3 = idx - 128*64 - 192*64;
    if (i3 >= 0 && i3 < 64) {
        float s = be2[i3];
        for (int t = 0; t < 128; t++) s += be1[t]*We2[t*64+i3];
        g_be[i3] = s;
    }
    if (i3 >= 64 && i3 < 128) {
        int c = i3 - 64; float s = bn2[c];
        for (int t = 0; t < 128; t++) s += bn1[t]*Wn2[t*64+c];
        g_bn[c] = s;
    }
}

// ---------------- K0b: pack concatenated edge-side weights (64 x 192) ----------------
__global__ void k_cat(const float* __restrict__ W_edges) {
    int idx = blockIdx.x*blockDim.x + threadIdx.x;
    if (idx >= 64*192) return;
    int j = idx / 192, c = idx % 192;
    float v;
    if (c < 64)       v = g_We[(64+j)*64 + c];          // We_edge
    else if (c < 128) v = g_Wn[(128+j)*64 + (c-64)];    // Wn_edge
    else              v = W_edges[(64+j)*64 + (c-128)]; // W_e_edge
    g_Wcat[idx] = v;
}

// ---------------- K1: node projections (B*N rows) ----------------
__global__ void k_nodeproj(const float* __restrict__ nodes) {
    __shared__ float sx[64];
    int row = blockIdx.x;               // b*N + i
    int c = threadIdx.x;                // 64 threads
    sx[c] = nodes[row*64 + c];
    __syncthreads();
    float s0 = 0.f, s1 = 0.f, s2 = 0.f;
    #pragma unroll 8
    for (int j = 0; j < 64; j++) {
        float x = sx[j];
        s0 += x * g_We[j*64 + c];
        s1 += x * g_Wn[j*64 + c];
        s2 += x * g_Wn[(64+j)*64 + c];
    }
    g_Pes[row*64+c] = s0;
    g_Pns[row*64+c] = s1;
    g_Pnd[row*64+c] = s2;
}

// ---------------- K2: edge projections GEMM (ROWS x 64) @ (64 x 192) ----------------
// Persistent blocks; weights staged once in SMEM; 8x6 register tile per thread.
__global__ void __launch_bounds__(256,2) k_edgeproj(const float* __restrict__ edges) {
    __shared__ float sW[64*192];
    __shared__ float sA[64][68];
    for (int idx = threadIdx.x; idx < 64*192; idx += 256) sW[idx] = g_Wcat[idx];
    int tx = threadIdx.x & 31, ty = threadIdx.x >> 5;
    const int NT = ROWS/64;
    for (int tile = blockIdx.x; tile < NT; tile += gridDim.x) {
        __syncthreads();
        const float4* src = (const float4*)(edges + (size_t)tile*64*64);
        for (int idx = threadIdx.x; idx < 64*16; idx += 256) {
            int r = idx >> 4, q = idx & 15;
            ((float4*)&sA[r][0])[q] = src[idx];
        }
        __syncthreads();
        float acc[8][6];
        #pragma unroll
        for (int a = 0; a < 8; a++)
            #pragma unroll
            for (int b = 0; b < 6; b++) acc[a][b] = 0.f;
        for (int j = 0; j < 64; j += 4) {
            float4 av[8];
            #pragma unroll
            for (int ri = 0; ri < 8; ri++) av[ri] = *(const float4*)&sA[ty + 8*ri][j];
            #pragma unroll
            for (int jj = 0; jj < 4; jj++) {
                float wv[6];
                #pragma unroll
                for (int ci = 0; ci < 6; ci++) wv[ci] = sW[(j+jj)*192 + tx + 32*ci];
                #pragma unroll
                for (int ri = 0; ri < 8; ri++) {
                    float a = (jj==0) ? av[ri].x : (jj==1) ? av[ri].y : (jj==2) ? av[ri].z : av[ri].w;
                    #pragma unroll
                    for (int ci = 0; ci < 6; ci++) acc[ri][ci] += a * wv[ci];
                }
            }
        }
        float* dst = g_Qe + (size_t)tile*64*192;
        #pragma unroll
        for (int ri = 0; ri < 8; ri++) {
            int r = ty + 8*ri;
            #pragma unroll
            for (int ci = 0; ci < 6; ci++)
                dst[(size_t)r*192 + tx + 32*ci] = acc[ri][ci];
        }
    }
}

// ---------------- K3: per-node scan (pair_e prefix mean, pair_n aggregation) ----------------
__global__ void k_scan() {
    int task = blockIdx.x;              // b*N + i
    int b = task >> 10, i = task & 1023;
    int c = threadIdx.x;                // 64 threads
    int w = node_w(i), ns = node_start(i), src0 = i - w;
    const float be = g_be[c], bn = g_bn[c];
    const float pnd = g_Pnd[task*64 + c];
    float run = 0.f, accn = 0.f;
    size_t ebase = (size_t)b*Ee + ns;
    int srow0 = (b << 10) + src0;
    for (int k = 0; k < w; k++) {
        size_t e = ebase + k;
        int srow = srow0 + k;
        float qe = g_Qe[e*192 + c];
        float qn = g_Qe[e*192 + 64 + c];
        float pe = g_Pes[srow*64 + c] + qe + be;  pe = pe > 0.f ? pe : 0.f;
        float pn = g_Pns[srow*64 + c] + pnd + qn + bn;  pn = pn > 0.f ? pn : 0.f;
        g_mean[e*64 + c] = (k > 0) ? run / (float)k : 0.f;
        run  += pe;
        accn += pn;
    }
    g_agg[task*64 + c] = accn / (float)(w > 0 ? w : 1);
}

// ---------------- K4: out_edges GEMM (ROWS x 64) @ (64 x 64) + addend + bias, ReLU ----------------
__global__ void __launch_bounds__(256,2) k_outedges(float* __restrict__ out,
                                                    const float* __restrict__ W_edges,
                                                    const float* __restrict__ bias) {
    __shared__ float sW[64*64];
    __shared__ float sA[64][68];
    __shared__ float sb[64];
    for (int idx = threadIdx.x; idx < 64*64; idx += 256) sW[idx] = W_edges[idx]; // rows 0..63 = W_e_mean
    if (threadIdx.x < 64) sb[threadIdx.x] = bias[threadIdx.x];
    int tx = threadIdx.x & 31, ty = threadIdx.x >> 5;
    const int NT = ROWS/64;
    for (int tile = blockIdx.x; tile < NT; tile += gridDim.x) {
        __syncthreads();
        const float4* src = (const float4*)(g_mean + (size_t)tile*64*64);
        for (int idx = threadIdx.x; idx < 64*16; idx += 256) {
            int r = idx >> 4, q = idx & 15;
            ((float4*)&sA[r][0])[q] = src[idx];
        }
        __syncthreads();
        float acc[8][2];
        #pragma unroll
        for (int a = 0; a < 8; a++) { acc[a][0] = 0.f; acc[a][1] = 0.f; }
        for (int j = 0; j < 64; j += 4) {
            float4 av[8];
            #pragma unroll
            for (int ri = 0; ri < 8; ri++) av[ri] = *(const float4*)&sA[ty + 8*ri][j];
            #pragma unroll
            for (int jj = 0; jj < 4; jj++) {
                float w0 = sW[(j+jj)*64 + tx];
                float w1 = sW[(j+jj)*64 + tx + 32];
                #pragma unroll
                for (int ri = 0; ri < 8; ri++) {
                    float a = (jj==0) ? av[ri].x : (jj==1) ? av[ri].y : (jj==2) ? av[ri].z : av[ri].w;
                    acc[ri][0] += a * w0;
                    acc[ri][1] += a * w1;
                }
            }
        }
        #pragma unroll
        for (int ri = 0; ri < 8; ri++) {
            size_t row = (size_t)tile*64 + ty + 8*ri;
            #pragma unroll
            for (int ci = 0; ci < 2; ci++) {
                int c = tx + 32*ci;
                float v = acc[ri][ci] + g_Qe[row*192 + 128 + c] + sb[c];
                out[row*64 + c] = v > 0.f ? v : 0.f;
            }
        }
    }
}

// ---------------- K5: out_nodes (B*N rows) ----------------
__global__ void k_outnodes(float* __restrict__ out, const float* __restrict__ nodes,
                           const float* __restrict__ W_nodes, const float* __restrict__ bias) {
    __shared__ float sx[128];
    int row = blockIdx.x;
    int c = threadIdx.x;                // 64 threads
    sx[c]      = g_agg[row*64 + c];
    sx[64 + c] = nodes[row*64 + c];
    __syncthreads();
    float s = bias[c];
    #pragma unroll 8
    for (int j = 0; j < 128; j++) s += sx[j] * W_nodes[j*64 + c];
    out[row*64 + c] = s > 0.f ? s : 0.f;
}

// ---------------- launch ----------------
extern "C" void kernel_launch(void* const* d_in, const int* in_sizes, int n_in,
                              void* d_out, int out_size) {
    const float* input_nodes = (const float*)d_in[0];
    const float* input_edges = (const float*)d_in[1];
    const float* Wn1 = (const float*)d_in[2];
    const float* bn1 = (const float*)d_in[3];
    const float* Wn2 = (const float*)d_in[4];
    const float* bn2 = (const float*)d_in[5];
    const float* We1 = (const float*)d_in[6];
    const float* be1 = (const float*)d_in[7];
    const float* We2 = (const float*)d_in[8];
    const float* be2 = (const float*)d_in[9];
    const float* W_nodes    = (const float*)d_in[10];
    const float* W_edges    = (const float*)d_in[11];
    const float* bias_edges = (const float*)d_in[12];

    float* out       = (float*)d_out;
    float* out_nodes = out;
    float* out_edges = out + (size_t)Bq*Nn*64;

    k_fuse<<<(128*64 + 192*64 + 128 + 255)/256, 256>>>(We1, We2, be1, be2, Wn1, bn1, Wn2, bn2);
    k_cat<<<(64*192 + 255)/256, 256>>>(W_edges);
    k_nodeproj<<<Bq*Nn, 64>>>(input_nodes);
    k_edgeproj<<<296, 256>>>(input_edges);
    k_scan<<<Bq*Nn, 64>>>();
    k_outedges<<<296, 256>>>(out_edges, W_edges, bias_edges);
    k_outnodes<<<Bq*Nn, 64>>>(out_nodes, input_nodes, W_nodes, bias_edges);
}

// round 2
// speedup vs baseline: 1.3627x; 1.3627x over previous
#include <cuda_runtime.h>

#define Bq 8
#define Nn 1024
#define Mw 64
#define Ee 63456
#define NROWS (Bq*Nn)          /* 8192 node rows */

// ---------------- device scratch ----------------
__device__ float g_We[128*64];          // fused We1@We2
__device__ float g_Wn[192*64];          // fused Wn1@Wn2
__device__ float g_be[64];
__device__ float g_bn[64];
__device__ float g_Wcat[64*192];        // edge-side:  [We_edge | Wn_edge | W_e_edge]
__device__ float g_WcatP[64*192];       // node-side:  [We_src  | Wn_src  | Wn_dst ]
__device__ float g_P[NROWS*192];        // node projections [Pes | Pns | Pnd]
__device__ float g_agg[NROWS*64];       // agg_n

__device__ __forceinline__ int node_w(int i)      { return i < Mw ? i : Mw; }
__device__ __forceinline__ int node_start(int i)  { return i <= Mw ? (i*(i-1))/2 : 2016 + (i-Mw)*Mw; }

// ---------------- K0: fuse the two (linear∘linear) MLPs ----------------
__global__ void k_fuse(const float* __restrict__ We1, const float* __restrict__ We2,
                       const float* __restrict__ be1, const float* __restrict__ be2,
                       const float* __restrict__ Wn1, const float* __restrict__ bn1,
                       const float* __restrict__ Wn2, const float* __restrict__ bn2) {
    int idx = blockIdx.x*blockDim.x + threadIdx.x;
    if (idx < 128*64) {
        int j = idx >> 6, c = idx & 63; float s = 0.f;
        for (int t = 0; t < 128; t++) s += We1[j*128+t]*We2[t*64+c];
        g_We[idx] = s;
    }
    int i2 = idx - 128*64;
    if (i2 >= 0 && i2 < 192*64) {
        int j = i2 >> 6, c = i2 & 63; float s = 0.f;
        for (int t = 0; t < 128; t++) s += Wn1[j*128+t]*Wn2[t*64+c];
        g_Wn[i2] = s;
    }
    int i3 = idx - 128*64 - 192*64;
    if (i3 >= 0 && i3 < 64) {
        float s = be2[i3];
        for (int t = 0; t < 128; t++) s += be1[t]*We2[t*64+i3];
        g_be[i3] = s;
    }
    if (i3 >= 64 && i3 < 128) {
        int c = i3 - 64; float s = bn2[c];
        for (int t = 0; t < 128; t++) s += bn1[t]*Wn2[t*64+c];
        g_bn[c] = s;
    }
}

// ---------------- K0b: pack concatenated weight blocks ----------------
__global__ void k_cat(const float* __restrict__ W_edges) {
    int idx = blockIdx.x*blockDim.x + threadIdx.x;
    if (idx >= 64*192) return;
    int j = idx / 192, c = idx % 192;
    float ve, vp;
    if (c < 64)       { ve = g_We[(64+j)*64 + c];          vp = g_We[j*64 + c]; }
    else if (c < 128) { ve = g_Wn[(128+j)*64 + (c-64)];    vp = g_Wn[j*64 + (c-64)]; }
    else              { ve = W_edges[(64+j)*64 + (c-128)]; vp = g_Wn[(64+j)*64 + (c-128)]; }
    g_Wcat[idx]  = ve;
    g_WcatP[idx] = vp;
}

// ---------------- K1: node projections GEMM (NROWS x 64) @ (64 x 192) ----------------
__global__ void __launch_bounds__(256,2) k_nodeproj(const float* __restrict__ A) {
    __shared__ float sW[64*192];
    __shared__ float sA[64][68];
    for (int idx = threadIdx.x; idx < 64*192; idx += 256) sW[idx] = g_WcatP[idx];
    int tx = threadIdx.x & 31, ty = threadIdx.x >> 5;
    const int NT = NROWS/64;
    for (int tile = blockIdx.x; tile < NT; tile += gridDim.x) {
        __syncthreads();
        const float4* src = (const float4*)(A + (size_t)tile*64*64);
        for (int idx = threadIdx.x; idx < 64*16; idx += 256) {
            int r = idx >> 4, q = idx & 15;
            ((float4*)&sA[r][0])[q] = src[idx];
        }
        __syncthreads();
        float acc[8][6];
        #pragma unroll
        for (int a = 0; a < 8; a++)
            #pragma unroll
            for (int b = 0; b < 6; b++) acc[a][b] = 0.f;
        for (int j = 0; j < 64; j += 4) {
            float4 av[8];
            #pragma unroll
            for (int ri = 0; ri < 8; ri++) av[ri] = *(const float4*)&sA[ty + 8*ri][j];
            #pragma unroll
            for (int jj = 0; jj < 4; jj++) {
                float wv[6];
                #pragma unroll
                for (int ci = 0; ci < 6; ci++) wv[ci] = sW[(j+jj)*192 + tx + 32*ci];
                #pragma unroll
                for (int ri = 0; ri < 8; ri++) {
                    float a = (jj==0) ? av[ri].x : (jj==1) ? av[ri].y : (jj==2) ? av[ri].z : av[ri].w;
                    #pragma unroll
                    for (int ci = 0; ci < 6; ci++) acc[ri][ci] += a * wv[ci];
                }
            }
        }
        float* dst = g_P + (size_t)tile*64*192;
        #pragma unroll
        for (int ri = 0; ri < 8; ri++) {
            int r = ty + 8*ri;
            #pragma unroll
            for (int ci = 0; ci < 6; ci++)
                dst[(size_t)r*192 + tx + 32*ci] = acc[ri][ci];
        }
    }
}

// ---------------- K2: fused per-node edge pipeline (persistent) ----------------
// Per node task: edges tile GEMM (w x 64)@(64 x 192), ReLU pairs, pair_n agg,
// exclusive prefix-mean of pair_e, then (w x 64)@(64 x 64) + Q3 + bias, ReLU.
__global__ void __launch_bounds__(256,2) k_fusededge(const float* __restrict__ edges,
                                                     const float* __restrict__ W_edges,
                                                     const float* __restrict__ bias,
                                                     float* __restrict__ out_edges) {
    __shared__ float sW1[64*192];      // Wcat
    __shared__ float sW2[64*64];       // W_mean (rows 0..63 of W_edges)
    __shared__ float sA[64][68];       // edges tile, later reused as mean matrix
    __shared__ float sPe[64][65];      // pair_e
    __shared__ float sred[8][64];      // pair_n partial sums
    __shared__ float slow[64];         // prefix half-total
    __shared__ float sbe[64], sbn[64], sbo[64];

    for (int idx = threadIdx.x; idx < 64*192; idx += 256) sW1[idx] = g_Wcat[idx];
    for (int idx = threadIdx.x; idx < 64*64;  idx += 256) sW2[idx] = W_edges[idx];
    if (threadIdx.x < 64) {
        sbe[threadIdx.x] = g_be[threadIdx.x];
        sbn[threadIdx.x] = g_bn[threadIdx.x];
        sbo[threadIdx.x] = bias[threadIdx.x];
    }
    int tx = threadIdx.x & 31, ty = threadIdx.x >> 5;
    int tid = threadIdx.x;

    for (int task = blockIdx.x; task < Bq*Nn; task += gridDim.x) {
        int b = task >> 10, i = task & 1023;
        int w = node_w(i), ns = node_start(i);
        size_t ebase = (size_t)b*Ee + ns;          // first edge row of this node
        int srow0 = (b << 10) + (i - w);           // first src node row

        __syncthreads();   // previous task fully done with smem
        // load edge rows (w x 64, contiguous)
        {
            const float4* src = (const float4*)(edges + ebase*64);
            for (int idx = tid; idx < w*16; idx += 256) {
                int r = idx >> 4, q = idx & 15;
                ((float4*)&sA[r][0])[q] = src[idx];
            }
        }
        __syncthreads();

        // GEMM1: Q = A @ Wcat   (acc[ri][0..1]=Qe, [2..3]=Qn, [4..5]=Q3)
        float acc[8][6];
        #pragma unroll
        for (int a = 0; a < 8; a++)
            #pragma unroll
            for (int c2 = 0; c2 < 6; c2++) acc[a][c2] = 0.f;
        for (int j = 0; j < 64; j += 4) {
            float4 av[8];
            #pragma unroll
            for (int ri = 0; ri < 8; ri++) av[ri] = *(const float4*)&sA[ty + 8*ri][j];
            #pragma unroll
            for (int jj = 0; jj < 4; jj++) {
                float wv[6];
                #pragma unroll
                for (int ci = 0; ci < 6; ci++) wv[ci] = sW1[(j+jj)*192 + tx + 32*ci];
                #pragma unroll
                for (int ri = 0; ri < 8; ri++) {
                    float a = (jj==0) ? av[ri].x : (jj==1) ? av[ri].y : (jj==2) ? av[ri].z : av[ri].w;
                    #pragma unroll
                    for (int ci = 0; ci < 6; ci++) acc[ri][ci] += a * wv[ci];
                }
            }
        }

        // ReLU pairs; pair_e -> sPe; pair_n partial column sums
        float pnd0 = g_P[(size_t)task*192 + 128 + tx];
        float pnd1 = g_P[(size_t)task*192 + 160 + tx];
        float np0 = 0.f, np1 = 0.f;
        #pragma unroll
        for (int ri = 0; ri < 8; ri++) {
            int r = ty + 8*ri;
            if (r < w) {
                size_t sr = (size_t)(srow0 + r)*192;
                float pe0 = acc[ri][0] + g_P[sr + tx]      + sbe[tx];
                float pe1 = acc[ri][1] + g_P[sr + tx + 32] + sbe[tx+32];
                sPe[r][tx]    = pe0 > 0.f ? pe0 : 0.f;
                sPe[r][tx+32] = pe1 > 0.f ? pe1 : 0.f;
                float pn0 = acc[ri][2] + g_P[sr + 64 + tx]  + pnd0 + sbn[tx];
                float pn1 = acc[ri][3] + g_P[sr + 96 + tx]  + pnd1 + sbn[tx+32];
                np0 += pn0 > 0.f ? pn0 : 0.f;
                np1 += pn1 > 0.f ? pn1 : 0.f;
            }
        }
        sred[ty][tx]      = np0;
        sred[ty][tx + 32] = np1;
        __syncthreads();

        // agg_n write
        if (tid < 64) {
            float s = 0.f;
            #pragma unroll
            for (int t = 0; t < 8; t++) s += sred[t][tid];
            g_agg[(size_t)task*64 + tid] = s / (float)(w > 0 ? w : 1);
        }

        // exclusive prefix of pair_e into sA (phase A: local scans)
        if (tid < 128) {
            int c = tid & 63, h = tid >> 6;
            int k0 = h*32, k1 = min(k0 + 32, w);
            float run = 0.f;
            for (int k = k0; k < k1; k++) {
                sA[k][c] = run;
                run += sPe[k][c];
            }
            if (h == 0) slow[c] = run;
        }
        __syncthreads();
        // phase B: add carry, divide by k
        if (tid < 128) {
            int c = tid & 63, h = tid >> 6;
            int k0 = h*32, k1 = min(k0 + 32, w);
            float base = (h == 1) ? slow[c] : 0.f;
            for (int k = k0; k < k1; k++) {
                float S = sA[k][c] + base;
                sA[k][c] = (k > 0) ? S / (float)k : 0.f;
            }
        }
        __syncthreads();

        // GEMM2: mean @ W_mean, epilogue + Q3 + bias, ReLU, write out
        float acc2[8][2];
        #pragma unroll
        for (int a = 0; a < 8; a++) { acc2[a][0] = 0.f; acc2[a][1] = 0.f; }
        for (int j = 0; j < 64; j += 4) {
            float4 av[8];
            #pragma unroll
            for (int ri = 0; ri < 8; ri++) av[ri] = *(const float4*)&sA[ty + 8*ri][j];
            #pragma unroll
            for (int jj = 0; jj < 4; jj++) {
                float w0 = sW2[(j+jj)*64 + tx];
                float w1 = sW2[(j+jj)*64 + tx + 32];
                #pragma unroll
                for (int ri = 0; ri < 8; ri++) {
                    float a = (jj==0) ? av[ri].x : (jj==1) ? av[ri].y : (jj==2) ? av[ri].z : av[ri].w;
                    acc2[ri][0] += a * w0;
                    acc2[ri][1] += a * w1;
                }
            }
        }
        #pragma unroll
        for (int ri = 0; ri < 8; ri++) {
            int r = ty + 8*ri;
            if (r < w) {
                size_t orow = (ebase + r)*64;
                float v0 = acc2[ri][0] + acc[ri][4] + sbo[tx];
                float v1 = acc2[ri][1] + acc[ri][5] + sbo[tx+32];
                out_edges[orow + tx]      = v0 > 0.f ? v0 : 0.f;
                out_edges[orow + tx + 32] = v1 > 0.f ? v1 : 0.f;
            }
        }
    }
}

// ---------------- K3: out_nodes (NROWS x 128) @ (128 x 64) ----------------
__global__ void __launch_bounds__(256,2) k_outnodes(float* __restrict__ out,
                                                    const float* __restrict__ nodes,
                                                    const float* __restrict__ W_nodes,
                                                    const float* __restrict__ bias) {
    __shared__ float sW[128*64];
    __shared__ float sA[64][132];
    __shared__ float sb[64];
    for (int idx = threadIdx.x; idx < 128*64; idx += 256) sW[idx] = W_nodes[idx];
    if (threadIdx.x < 64) sb[threadIdx.x] = bias[threadIdx.x];
    int tx = threadIdx.x & 31, ty = threadIdx.x >> 5;
    int tile = blockIdx.x;   // NROWS/64 = 128 tiles, grid = 128
    {
        const float4* sa = (const float4*)(g_agg + (size_t)tile*64*64);
        const float4* sn = (const float4*)(nodes + (size_t)tile*64*64);
        for (int idx = threadIdx.x; idx < 64*16; idx += 256) {
            int r = idx >> 4, q = idx & 15;
            ((float4*)&sA[r][0])[q]  = sa[idx];
            ((float4*)&sA[r][64])[q] = sn[idx];
        }
    }
    __syncthreads();
    float acc[8][2];
    #pragma unroll
    for (int a = 0; a < 8; a++) { acc[a][0] = 0.f; acc[a][1] = 0.f; }
    for (int j = 0; j < 128; j += 4) {
        float4 av[8];
        #pragma unroll
        for (int ri = 0; ri < 8; ri++) av[ri] = *(const float4*)&sA[ty + 8*ri][j];
        #pragma unroll
        for (int jj = 0; jj < 4; jj++) {
            float w0 = sW[(j+jj)*64 + tx];
            float w1 = sW[(j+jj)*64 + tx + 32];
            #pragma unroll
            for (int ri = 0; ri < 8; ri++) {
                float a = (jj==0) ? av[ri].x : (jj==1) ? av[ri].y : (jj==2) ? av[ri].z : av[ri].w;
                acc[ri][0] += a * w0;
                acc[ri][1] += a * w1;
            }
        }
    }
    #pragma unroll
    for (int ri = 0; ri < 8; ri++) {
        size_t row = (size_t)tile*64 + ty + 8*ri;
        float v0 = acc[ri][0] + sb[tx];
        float v1 = acc[ri][1] + sb[tx+32];
        out[row*64 + tx]      = v0 > 0.f ? v0 : 0.f;
        out[row*64 + tx + 32] = v1 > 0.f ? v1 : 0.f;
    }
}

// ---------------- launch ----------------
extern "C" void kernel_launch(void* const* d_in, const int* in_sizes, int n_in,
                              void* d_out, int out_size) {
    const float* input_nodes = (const float*)d_in[0];
    const float* input_edges = (const float*)d_in[1];
    const float* Wn1 = (const float*)d_in[2];
    const float* bn1 = (const float*)d_in[3];
    const float* Wn2 = (const float*)d_in[4];
    const float* bn2 = (const float*)d_in[5];
    const float* We1 = (const float*)d_in[6];
    const float* be1 = (const float*)d_in[7];
    const float* We2 = (const float*)d_in[8];
    const float* be2 = (const float*)d_in[9];
    const float* W_nodes    = (const float*)d_in[10];
    const float* W_edges    = (const float*)d_in[11];
    const float* bias_edges = (const float*)d_in[12];

    float* out       = (float*)d_out;
    float* out_nodes = out;
    float* out_edges = out + (size_t)Bq*Nn*64;

    k_fuse<<<(128*64 + 192*64 + 128 + 255)/256, 256>>>(We1, We2, be1, be2, Wn1, bn1, Wn2, bn2);
    k_cat<<<(64*192 + 255)/256, 256>>>(W_edges);
    k_nodeproj<<<128, 256>>>(input_nodes);
    k_fusededge<<<296, 256>>>(input_edges, W_edges, bias_edges, out_edges);
    k_outnodes<<<128, 256>>>(out_nodes, input_nodes, W_nodes, bias_edges);
}

// round 3
// speedup vs baseline: 1.8153x; 1.3322x over previous
#include <cuda_runtime.h>

#define Bq 8
#define Nn 1024
#define Mw 64
#define Ee 63456
#define NROWS (Bq*Nn)          /* 8192 node rows */

typedef unsigned long long ull;

// ---------------- device scratch ----------------
__device__ float g_We[128*64];          // fused We1@We2
__device__ float g_Wn[192*64];          // fused Wn1@Wn2
__device__ float g_be[64];
__device__ float g_bn[64];
__device__ float g_Wcat[64*192];        // edge-side:  [We_edge | Wn_edge | W_e_edge]
__device__ float g_WcatP[64*192];       // node-side:  [We_src  | Wn_src  | Wn_dst ]
__device__ float g_P[NROWS*192];        // node projections [Pes | Pns | Pnd]
__device__ float g_agg[NROWS*64];       // agg_n

__device__ __forceinline__ int node_w(int i)      { return i < Mw ? i : Mw; }
__device__ __forceinline__ int node_start(int i)  { return i <= Mw ? (i*(i-1))/2 : 2016 + (i-Mw)*Mw; }

// ---------------- packed fp32x2 helpers ----------------
__device__ __forceinline__ void fma2(ull &d, ull a, ull b) {
    asm("fma.rn.f32x2 %0, %1, %2, %0;" : "+l"(d) : "l"(a), "l"(b));
}
__device__ __forceinline__ ull bcast2(float x) {
    ull r; asm("mov.b64 %0, {%1, %1};" : "=l"(r) : "f"(x)); return r;
}
__device__ __forceinline__ float2 unpk(ull v) {
    float2 r; asm("mov.b64 {%0, %1}, %2;" : "=f"(r.x), "=f"(r.y) : "l"(v)); return r;
}

// ---------------- K0: fuse the two (linear∘linear) MLPs ----------------
__global__ void k_fuse(const float* __restrict__ We1, const float* __restrict__ We2,
                       const float* __restrict__ be1, const float* __restrict__ be2,
                       const float* __restrict__ Wn1, const float* __restrict__ bn1,
                       const float* __restrict__ Wn2, const float* __restrict__ bn2) {
    int idx = blockIdx.x*blockDim.x + threadIdx.x;
    if (idx < 128*64) {
        int j = idx >> 6, c = idx & 63; float s = 0.f;
        for (int t = 0; t < 128; t++) s += We1[j*128+t]*We2[t*64+c];
        g_We[idx] = s;
    }
    int i2 = idx - 128*64;
    if (i2 >= 0 && i2 < 192*64) {
        int j = i2 >> 6, c = i2 & 63; float s = 0.f;
        for (int t = 0; t < 128; t++) s += Wn1[j*128+t]*Wn2[t*64+c];
        g_Wn[i2] = s;
    }
    int i3 = idx - 128*64 - 192*64;
    if (i3 >= 0 && i3 < 64) {
        float s = be2[i3];
        for (int t = 0; t < 128; t++) s += be1[t]*We2[t*64+i3];
        g_be[i3] = s;
    }
    if (i3 >= 64 && i3 < 128) {
        int c = i3 - 64; float s = bn2[c];
        for (int t = 0; t < 128; t++) s += bn1[t]*Wn2[t*64+c];
        g_bn[c] = s;
    }
}

// ---------------- K0b: pack concatenated weight blocks ----------------
__global__ void k_cat(const float* __restrict__ W_edges) {
    int idx = blockIdx.x*blockDim.x + threadIdx.x;
    if (idx >= 64*192) return;
    int j = idx / 192, c = idx % 192;
    float ve, vp;
    if (c < 64)       { ve = g_We[(64+j)*64 + c];          vp = g_We[j*64 + c]; }
    else if (c < 128) { ve = g_Wn[(128+j)*64 + (c-64)];    vp = g_Wn[j*64 + (c-64)]; }
    else              { ve = W_edges[(64+j)*64 + (c-128)]; vp = g_Wn[(64+j)*64 + (c-128)]; }
    g_Wcat[idx]  = ve;
    g_WcatP[idx] = vp;
}

// ---------------- K1: node projections GEMM (NROWS x 64) @ (64 x 192) ----------------
__global__ void __launch_bounds__(256,2) k_nodeproj(const float* __restrict__ A) {
    __shared__ float sW[64*192];
    __shared__ float sA[64][68];
    for (int idx = threadIdx.x; idx < 64*192; idx += 256) sW[idx] = g_WcatP[idx];
    int tx = threadIdx.x & 31, ty = threadIdx.x >> 5;
    const int NT = NROWS/64;
    for (int tile = blockIdx.x; tile < NT; tile += gridDim.x) {
        __syncthreads();
        const float4* src = (const float4*)(A + (size_t)tile*64*64);
        for (int idx = threadIdx.x; idx < 64*16; idx += 256) {
            int r = idx >> 4, q = idx & 15;
            ((float4*)&sA[r][0])[q] = src[idx];
        }
        __syncthreads();
        float acc[8][6];
        #pragma unroll
        for (int a = 0; a < 8; a++)
            #pragma unroll
            for (int b = 0; b < 6; b++) acc[a][b] = 0.f;
        for (int j = 0; j < 64; j += 4) {
            float4 av[8];
            #pragma unroll
            for (int ri = 0; ri < 8; ri++) av[ri] = *(const float4*)&sA[ty + 8*ri][j];
            #pragma unroll
            for (int jj = 0; jj < 4; jj++) {
                float wv[6];
                #pragma unroll
                for (int ci = 0; ci < 6; ci++) wv[ci] = sW[(j+jj)*192 + tx + 32*ci];
                #pragma unroll
                for (int ri = 0; ri < 8; ri++) {
                    float a = (jj==0) ? av[ri].x : (jj==1) ? av[ri].y : (jj==2) ? av[ri].z : av[ri].w;
                    #pragma unroll
                    for (int ci = 0; ci < 6; ci++) acc[ri][ci] += a * wv[ci];
                }
            }
        }
        float* dst = g_P + (size_t)tile*64*192;
        #pragma unroll
        for (int ri = 0; ri < 8; ri++) {
            int r = ty + 8*ri;
            #pragma unroll
            for (int ci = 0; ci < 6; ci++)
                dst[(size_t)r*192 + tx + 32*ci] = acc[ri][ci];
        }
    }
}

// ---------------- K2: fused per-node edge pipeline (persistent, fp32x2) ----------------
__global__ void __launch_bounds__(256,2) k_fusededge(const float* __restrict__ edges,
                                                     const float* __restrict__ W_edges,
                                                     const float* __restrict__ bias,
                                                     float* __restrict__ out_edges) {
    __shared__ float sW1[64*192];                    // Wcat (K-major rows j)
    __shared__ float sW2[64*64];                     // W_mean
    __shared__ __align__(16) float sAT[64][66];      // edges tile, TRANSPOSED [j][r]
    __shared__ __align__(16) float sPeT[64][66];     // pair_e, TRANSPOSED [c][r]
    __shared__ float sred[8][64];                    // pair_n partial sums
    __shared__ ull  swred[8][32];                    // per-warp prefix totals (col pair)
    __shared__ float sbe[64], sbn[64], sbo[64], srcp[64];

    for (int idx = threadIdx.x; idx < 64*192; idx += 256) sW1[idx] = g_Wcat[idx];
    for (int idx = threadIdx.x; idx < 64*64;  idx += 256) sW2[idx] = W_edges[idx];
    if (threadIdx.x < 64) {
        sbe[threadIdx.x] = g_be[threadIdx.x];
        sbn[threadIdx.x] = g_bn[threadIdx.x];
        sbo[threadIdx.x] = bias[threadIdx.x];
        srcp[threadIdx.x] = 1.0f / (float)(threadIdx.x > 0 ? threadIdx.x : 1);
    }
    int tx = threadIdx.x & 31, ty = threadIdx.x >> 5;
    int tid = threadIdx.x;
    int r0t = 8*ty;                                  // this warp's first row

    for (int task = blockIdx.x; task < Bq*Nn; task += gridDim.x) {
        int b = task >> 10, i = task & 1023;
        int w = node_w(i), ns = node_start(i);
        size_t ebase = (size_t)b*Ee + ns;            // first edge row of this node
        int srow0 = (b << 10) + (i - w);             // first src node row

        __syncthreads();   // previous task fully done with smem

        // ---- prefetch per-row node projections (consumed after GEMM1) ----
        float pf[8][4], pnd0, pnd1;
        {
            size_t pb = (size_t)task*192;
            pnd0 = g_P[pb + 128 + tx];
            pnd1 = g_P[pb + 160 + tx];
            #pragma unroll
            for (int ri = 0; ri < 8; ri++) {
                size_t sr = (size_t)(srow0 + r0t + ri)*192;
                pf[ri][0] = g_P[sr + tx];
                pf[ri][1] = g_P[sr + 32 + tx];
                pf[ri][2] = g_P[sr + 64 + tx];
                pf[ri][3] = g_P[sr + 96 + tx];
            }
        }

        // ---- load edge rows (w x 64) transposed into sAT[j][r] ----
        {
            const float4* src = (const float4*)(edges + ebase*64);
            for (int idx = tid; idx < w*16; idx += 256) {
                int r = idx >> 4, q = idx & 15;
                float4 v = src[idx];
                int j = 4*q;
                sAT[j+0][r] = v.x; sAT[j+1][r] = v.y;
                sAT[j+2][r] = v.z; sAT[j+3][r] = v.w;
            }
        }
        __syncthreads();

        // ---- GEMM1: Q = A @ Wcat, row-pair fp32x2 ----
        // acc[q][ci]: rows (8ty+2q, 8ty+2q+1), col tx+32*ci
        ull acc[4][6];
        #pragma unroll
        for (int q = 0; q < 4; q++)
            #pragma unroll
            for (int c2 = 0; c2 < 6; c2++) acc[q][c2] = 0ull;
        #pragma unroll 8
        for (int j = 0; j < 64; j++) {
            ull a2[4];
            #pragma unroll
            for (int q = 0; q < 4; q++) a2[q] = *(const ull*)&sAT[j][r0t + 2*q];
            #pragma unroll
            for (int ci = 0; ci < 6; ci++) {
                ull w2 = bcast2(sW1[j*192 + tx + 32*ci]);
                #pragma unroll
                for (int q = 0; q < 4; q++) fma2(acc[q][ci], a2[q], w2);
            }
        }

        // ---- epilogue: ReLU pairs; pair_e -> sPeT (transposed, zero-padded);
        //      pair_n column partial sums; keep Q3 in regs ----
        float q30[8], q31[8];
        float np0 = 0.f, np1 = 0.f;
        #pragma unroll
        for (int q = 0; q < 4; q++) {
            float2 e0 = unpk(acc[q][0]);
            float2 e1 = unpk(acc[q][1]);
            float2 n0 = unpk(acc[q][2]);
            float2 n1 = unpk(acc[q][3]);
            float2 t0 = unpk(acc[q][4]);
            float2 t1 = unpk(acc[q][5]);
            q30[2*q] = t0.x; q30[2*q+1] = t0.y;
            q31[2*q] = t1.x; q31[2*q+1] = t1.y;
            #pragma unroll
            for (int h = 0; h < 2; h++) {
                int rr = 2*q + h;
                int r  = r0t + rr;
                float ev0 = h ? e0.y : e0.x;
                float ev1 = h ? e1.y : e1.x;
                float nv0 = h ? n0.y : n0.x;
                float nv1 = h ? n1.y : n1.x;
                if (r < w) {
                    float pe0 = ev0 + pf[rr][0] + sbe[tx];
                    float pe1 = ev1 + pf[rr][1] + sbe[tx+32];
                    sPeT[tx][r]    = pe0 > 0.f ? pe0 : 0.f;
                    sPeT[tx+32][r] = pe1 > 0.f ? pe1 : 0.f;
                    float pn0 = nv0 + pf[rr][2] + pnd0 + sbn[tx];
                    float pn1 = nv1 + pf[rr][3] + pnd1 + sbn[tx+32];
                    np0 += pn0 > 0.f ? pn0 : 0.f;
                    np1 += pn1 > 0.f ? pn1 : 0.f;
                } else {
                    sPeT[tx][r]    = 0.f;
                    sPeT[tx+32][r] = 0.f;
                }
            }
        }
        sred[ty][tx]      = np0;
        sred[ty][tx + 32] = np1;
        __syncthreads();

        // agg_n write (overlaps with start of GEMM2 in other threads' slots)
        if (tid < 64) {
            float s = 0.f;
            #pragma unroll
            for (int t = 0; t < 8; t++) s += sred[t][tid];
            g_agg[(size_t)task*64 + tid] = s / (float)(w > 0 ? w : 1);
        }

        // ---- GEMM2: R = pair_e @ W_mean  (prefix commutes with GEMM) ----
        ull acc2[4][2];
        #pragma unroll
        for (int q = 0; q < 4; q++) { acc2[q][0] = 0ull; acc2[q][1] = 0ull; }
        #pragma unroll 8
        for (int j = 0; j < 64; j++) {
            ull a2[4];
            #pragma unroll
            for (int q = 0; q < 4; q++) a2[q] = *(const ull*)&sPeT[j][r0t + 2*q];
            ull w20 = bcast2(sW2[j*64 + tx]);
            ull w21 = bcast2(sW2[j*64 + tx + 32]);
            #pragma unroll
            for (int q = 0; q < 4; q++) {
                fma2(acc2[q][0], a2[q], w20);
                fma2(acc2[q][1], a2[q], w21);
            }
        }

        // ---- exclusive row-prefix of R (in-register + warp carries) ----
        float s0[8], s1[8];
        #pragma unroll
        for (int q = 0; q < 4; q++) {
            float2 v0 = unpk(acc2[q][0]);
            float2 v1 = unpk(acc2[q][1]);
            s0[2*q] = v0.x; s0[2*q+1] = v0.y;
            s1[2*q] = v1.x; s1[2*q+1] = v1.y;
        }
        float ex0[8], ex1[8], run0 = 0.f, run1 = 0.f;
        #pragma unroll
        for (int ri = 0; ri < 8; ri++) {
            ex0[ri] = run0; run0 += s0[ri];
            ex1[ri] = run1; run1 += s1[ri];
        }
        {
            ull tot; asm("mov.b64 %0, {%1, %2};" : "=l"(tot) : "f"(run0), "f"(run1));
            swred[ty][tx] = tot;
        }
        __syncthreads();
        float c0 = 0.f, c1 = 0.f;
        for (int t = 0; t < ty; t++) {
            float2 v = unpk(swred[t][tx]);
            c0 += v.x; c1 += v.y;
        }

        // ---- final: mean-scale + Q3 + bias, ReLU, store ----
        #pragma unroll
        for (int ri = 0; ri < 8; ri++) {
            int r = r0t + ri;
            if (r < w) {
                float rc = srcp[r];
                size_t orow = (ebase + r)*64;
                float v0 = (ex0[ri] + c0)*rc + q30[ri] + sbo[tx];
                float v1 = (ex1[ri] + c1)*rc + q31[ri] + sbo[tx+32];
                out_edges[orow + tx]      = v0 > 0.f ? v0 : 0.f;
                out_edges[orow + tx + 32] = v1 > 0.f ? v1 : 0.f;
            }
        }
    }
}

// ---------------- K3: out_nodes (NROWS x 128) @ (128 x 64) ----------------
__global__ void __launch_bounds__(256,2) k_outnodes(float* __restrict__ out,
                                                    const float* __restrict__ nodes,
                                                    const float* __restrict__ W_nodes,
                                                    const float* __restrict__ bias) {
    __shared__ float sW[128*64];
    __shared__ float sA[64][132];
    __shared__ float sb[64];
    for (int idx = threadIdx.x; idx < 128*64; idx += 256) sW[idx] = W_nodes[idx];
    if (threadIdx.x < 64) sb[threadIdx.x] = bias[threadIdx.x];
    int tx = threadIdx.x & 31, ty = threadIdx.x >> 5;
    int tile = blockIdx.x;
    {
        const float4* sa = (const float4*)(g_agg + (size_t)tile*64*64);
        const float4* sn = (const float4*)(nodes + (size_t)tile*64*64);
        for (int idx = threadIdx.x; idx < 64*16; idx += 256) {
            int r = idx >> 4, q = idx & 15;
            ((float4*)&sA[r][0])[q]  = sa[idx];
            ((float4*)&sA[r][64])[q] = sn[idx];
        }
    }
    __syncthreads();
    float acc[8][2];
    #pragma unroll
    for (int a = 0; a < 8; a++) { acc[a][0] = 0.f; acc[a][1] = 0.f; }
    for (int j = 0; j < 128; j += 4) {
        float4 av[8];
        #pragma unroll
        for (int ri = 0; ri < 8; ri++) av[ri] = *(const float4*)&sA[ty + 8*ri][j];
        #pragma unroll
        for (int jj = 0; jj < 4; jj++) {
            float w0 = sW[(j+jj)*64 + tx];
            float w1 = sW[(j+jj)*64 + tx + 32];
            #pragma unroll
            for (int ri = 0; ri < 8; ri++) {
                float a = (jj==0) ? av[ri].x : (jj==1) ? av[ri].y : (jj==2) ? av[ri].z : av[ri].w;
                acc[ri][0] += a * w0;
                acc[ri][1] += a * w1;
            }
        }
    }
    #pragma unroll
    for (int ri = 0; ri < 8; ri++) {
        size_t row = (size_t)tile*64 + ty + 8*ri;
        float v0 = acc[ri][0] + sb[tx];
        float v1 = acc[ri][1] + sb[tx+32];
        out[row*64 + tx]      = v0 > 0.f ? v0 : 0.f;
        out[row*64 + tx + 32] = v1 > 0.f ? v1 : 0.f;
    }
}

// ---------------- launch ----------------
extern "C" void kernel_launch(void* const* d_in, const int* in_sizes, int n_in,
                              void* d_out, int out_size) {
    const float* input_nodes = (const float*)d_in[0];
    const float* input_edges = (const float*)d_in[1];
    const float* Wn1 = (const float*)d_in[2];
    const float* bn1 = (const float*)d_in[3];
    const float* Wn2 = (const float*)d_in[4];
    const float* bn2 = (const float*)d_in[5];
    const float* We1 = (const float*)d_in[6];
    const float* be1 = (const float*)d_in[7];
    const float* We2 = (const float*)d_in[8];
    const float* be2 = (const float*)d_in[9];
    const float* W_nodes    = (const float*)d_in[10];
    const float* W_edges    = (const float*)d_in[11];
    const float* bias_edges = (const float*)d_in[12];

    float* out       = (float*)d_out;
    float* out_nodes = out;
    float* out_edges = out + (size_t)Bq*Nn*64;

    k_fuse<<<(128*64 + 192*64 + 128 + 255)/256, 256>>>(We1, We2, be1, be2, Wn1, bn1, Wn2, bn2);
    k_cat<<<(64*192 + 255)/256, 256>>>(W_edges);
    k_nodeproj<<<128, 256>>>(input_nodes);
    k_fusededge<<<296, 256>>>(input_edges, W_edges, bias_edges, out_edges);
    k_outnodes<<<128, 256>>>(out_nodes, input_nodes, W_nodes, bias_edges);
}

// round 4
// speedup vs baseline: 1.9860x; 1.0941x over previous
#include <cuda_runtime.h>

#define Bq 8
#define Nn 1024
#define Mw 64
#define Ee 63456
#define NROWS (Bq*Nn)          /* 8192 node rows */

typedef unsigned long long ull;

// ---------------- device scratch ----------------
__device__ float g_We[128*64];          // fused We1@We2
__device__ float g_Wn[192*64];          // fused Wn1@Wn2
__device__ float g_be[64];
__device__ float g_bn[64];
__device__ float g_Wcat[64*192];        // edge-side:  [We_edge | Wn_edge | W_e_edge]
__device__ float g_WcatP[64*192];       // node-side:  [We_src  | Wn_src  | Wn_dst ]
__device__ float g_P[NROWS*192];        // node projections [Pes | Pns | Pnd]
__device__ float g_agg[NROWS*64];       // agg_n

__device__ __forceinline__ int node_w(int i)      { return i < Mw ? i : Mw; }
__device__ __forceinline__ int node_start(int i)  { return i <= Mw ? (i*(i-1))/2 : 2016 + (i-Mw)*Mw; }

// ---------------- packed fp32x2 helpers ----------------
__device__ __forceinline__ void fma2(ull &d, ull a, ull b) {
    asm("fma.rn.f32x2 %0, %1, %2, %0;" : "+l"(d) : "l"(a), "l"(b));
}
__device__ __forceinline__ ull bcast2(float x) {
    ull r; asm("mov.b64 %0, {%1, %1};" : "=l"(r) : "f"(x)); return r;
}
__device__ __forceinline__ float2 unpk(ull v) {
    float2 r; asm("mov.b64 {%0, %1}, %2;" : "=f"(r.x), "=f"(r.y) : "l"(v)); return r;
}
__device__ __forceinline__ ull pk(float x, float y) {
    ull r; asm("mov.b64 %0, {%1, %2};" : "=l"(r) : "f"(x), "f"(y)); return r;
}

// ---------------- K0: fuse the two (linear∘linear) MLPs ----------------
__global__ void k_fuse(const float* __restrict__ We1, const float* __restrict__ We2,
                       const float* __restrict__ be1, const float* __restrict__ be2,
                       const float* __restrict__ Wn1, const float* __restrict__ bn1,
                       const float* __restrict__ Wn2, const float* __restrict__ bn2) {
    int idx = blockIdx.x*blockDim.x + threadIdx.x;
    if (idx < 128*64) {
        int j = idx >> 6, c = idx & 63; float s = 0.f;
        for (int t = 0; t < 128; t++) s += We1[j*128+t]*We2[t*64+c];
        g_We[idx] = s;
    }
    int i2 = idx - 128*64;
    if (i2 >= 0 && i2 < 192*64) {
        int j = i2 >> 6, c = i2 & 63; float s = 0.f;
        for (int t = 0; t < 128; t++) s += Wn1[j*128+t]*Wn2[t*64+c];
        g_Wn[i2] = s;
    }
    int i3 = idx - 128*64 - 192*64;
    if (i3 >= 0 && i3 < 64) {
        float s = be2[i3];
        for (int t = 0; t < 128; t++) s += be1[t]*We2[t*64+i3];
        g_be[i3] = s;
    }
    if (i3 >= 64 && i3 < 128) {
        int c = i3 - 64; float s = bn2[c];
        for (int t = 0; t < 128; t++) s += bn1[t]*Wn2[t*64+c];
        g_bn[c] = s;
    }
}

// ---------------- K0b: pack concatenated weight blocks ----------------
__global__ void k_cat(const float* __restrict__ W_edges) {
    int idx = blockIdx.x*blockDim.x + threadIdx.x;
    if (idx >= 64*192) return;
    int j = idx / 192, c = idx % 192;
    float ve, vp;
    if (c < 64)       { ve = g_We[(64+j)*64 + c];          vp = g_We[j*64 + c]; }
    else if (c < 128) { ve = g_Wn[(128+j)*64 + (c-64)];    vp = g_Wn[j*64 + (c-64)]; }
    else              { ve = W_edges[(64+j)*64 + (c-128)]; vp = g_Wn[(64+j)*64 + (c-128)]; }
    g_Wcat[idx]  = ve;
    g_WcatP[idx] = vp;
}

// ---------------- K1: node projections GEMM (NROWS x 64) @ (64 x 192) ----------------
__global__ void __launch_bounds__(256,2) k_nodeproj(const float* __restrict__ A) {
    __shared__ float sW[64*192];
    __shared__ float sA[64][68];
    for (int idx = threadIdx.x; idx < 64*192; idx += 256) sW[idx] = g_WcatP[idx];
    int tx = threadIdx.x & 31, ty = threadIdx.x >> 5;
    const int NT = NROWS/64;
    for (int tile = blockIdx.x; tile < NT; tile += gridDim.x) {
        __syncthreads();
        const float4* src = (const float4*)(A + (size_t)tile*64*64);
        for (int idx = threadIdx.x; idx < 64*16; idx += 256) {
            int r = idx >> 4, q = idx & 15;
            ((float4*)&sA[r][0])[q] = src[idx];
        }
        __syncthreads();
        float acc[8][6];
        #pragma unroll
        for (int a = 0; a < 8; a++)
            #pragma unroll
            for (int b = 0; b < 6; b++) acc[a][b] = 0.f;
        for (int j = 0; j < 64; j += 4) {
            float4 av[8];
            #pragma unroll
            for (int ri = 0; ri < 8; ri++) av[ri] = *(const float4*)&sA[ty + 8*ri][j];
            #pragma unroll
            for (int jj = 0; jj < 4; jj++) {
                float wv[6];
                #pragma unroll
                for (int ci = 0; ci < 6; ci++) wv[ci] = sW[(j+jj)*192 + tx + 32*ci];
                #pragma unroll
                for (int ri = 0; ri < 8; ri++) {
                    float a = (jj==0) ? av[ri].x : (jj==1) ? av[ri].y : (jj==2) ? av[ri].z : av[ri].w;
                    #pragma unroll
                    for (int ci = 0; ci < 6; ci++) acc[ri][ci] += a * wv[ci];
                }
            }
        }
        float* dst = g_P + (size_t)tile*64*192;
        #pragma unroll
        for (int ri = 0; ri < 8; ri++) {
            int r = ty + 8*ri;
            #pragma unroll
            for (int ci = 0; ci < 6; ci++)
                dst[(size_t)r*192 + tx + 32*ci] = acc[ri][ci];
        }
    }
}

// ---------------- K2: fused per-node edge pipeline (persistent, fp32x2, col-pairs) ----------------
// Thread (tx,ty): rows r0t..r0t+7 (4 row-pairs), cols {64g + 2tx, 64g + 2tx + 1}.
__global__ void __launch_bounds__(256,2) k_fusededge(const float* __restrict__ edges,
                                                     const float* __restrict__ W_edges,
                                                     const float* __restrict__ bias,
                                                     float* __restrict__ out_edges) {
    __shared__ float sW1[64*192];                    // Wcat (K-major rows j)
    __shared__ float sW2[64*64];                     // W_mean
    __shared__ __align__(16) float sAT[64][66];      // edges tile, TRANSPOSED [j][r]
    __shared__ __align__(16) float sPeT[64][66];     // pair_e, TRANSPOSED [c][r]
    __shared__ float sred[8][64];                    // pair_n partial sums
    __shared__ ull  swred[8][32];                    // per-warp prefix totals (col pair)
    __shared__ float sbe[64], sbn[64], sbo[64], srcp[64];

    for (int idx = threadIdx.x; idx < 64*192; idx += 256) sW1[idx] = g_Wcat[idx];
    for (int idx = threadIdx.x; idx < 64*64;  idx += 256) sW2[idx] = W_edges[idx];
    if (threadIdx.x < 64) {
        sbe[threadIdx.x] = g_be[threadIdx.x];
        sbn[threadIdx.x] = g_bn[threadIdx.x];
        sbo[threadIdx.x] = bias[threadIdx.x];
        srcp[threadIdx.x] = 1.0f / (float)(threadIdx.x > 0 ? threadIdx.x : 1);
    }
    int tx = threadIdx.x & 31, ty = threadIdx.x >> 5;
    int tid = threadIdx.x;
    int r0t = 8*ty;                                  // this warp's first row
    int c0 = 2*tx;                                   // this thread's first col in each 64-group

    for (int task = blockIdx.x; task < Bq*Nn; task += gridDim.x) {
        int b = task >> 10, i = task & 1023;
        int w = node_w(i), ns = node_start(i);
        size_t ebase = (size_t)b*Ee + ns;            // first edge row of this node
        int srow0 = (b << 10) + (i - w);             // first src node row

        __syncthreads();   // previous task fully done with smem

        // ---- load edge rows (w x 64) transposed into sAT[j][r] ----
        {
            const float4* src = (const float4*)(edges + ebase*64);
            for (int idx = tid; idx < w*16; idx += 256) {
                int r = idx >> 4, q = idx & 15;
                float4 v = src[idx];
                int j = 4*q;
                sAT[j+0][r] = v.x; sAT[j+1][r] = v.y;
                sAT[j+2][r] = v.z; sAT[j+3][r] = v.w;
            }
        }
        __syncthreads();

        // ---- GEMM1: Q = A @ Wcat, row-pair fp32x2, col-pair W loads ----
        // acc[q][2g+h]: rows (r0t+2q, r0t+2q+1), col 64g + c0 + h
        ull acc[4][6];
        #pragma unroll
        for (int q = 0; q < 4; q++)
            #pragma unroll
            for (int c2 = 0; c2 < 6; c2++) acc[q][c2] = 0ull;
        #pragma unroll 8
        for (int j = 0; j < 64; j++) {
            ull a2[4];
            #pragma unroll
            for (int q = 0; q < 4; q++) a2[q] = *(const ull*)&sAT[j][r0t + 2*q];
            #pragma unroll
            for (int g = 0; g < 3; g++) {
                float2 wp = *(const float2*)&sW1[j*192 + 64*g + c0];
                ull w20 = bcast2(wp.x);
                ull w21 = bcast2(wp.y);
                #pragma unroll
                for (int q = 0; q < 4; q++) {
                    fma2(acc[q][2*g+0], a2[q], w20);
                    fma2(acc[q][2*g+1], a2[q], w21);
                }
            }
        }

        // ---- per-row node projections (float2 over col pair) ----
        float2 pnd0, pnd1, pfe[8], pfn[8];
        {
            size_t pb = (size_t)task*192;
            pnd0 = *(const float2*)&g_P[pb + 128 + c0];   // cols (128+c0, 128+c0+1) -> Pnd pair
            pnd1 = pnd0;  // same pair; kept for clarity of col0/col1 below
            #pragma unroll
            for (int ri = 0; ri < 8; ri++) {
                size_t sr = (size_t)(srow0 + r0t + ri)*192;
                pfe[ri] = *(const float2*)&g_P[sr + c0];        // Pes cols (c0, c0+1)
                pfn[ri] = *(const float2*)&g_P[sr + 64 + c0];   // Pns cols
            }
        }
        float2 be2v = *(const float2*)&sbe[c0];
        float2 bn2v = *(const float2*)&sbn[c0];

        // ---- epilogue: ReLU pairs; pair_e -> sPeT row-pair STS.64; pair_n col sums ----
        float np0 = 0.f, np1 = 0.f;
        #pragma unroll
        for (int q = 0; q < 4; q++) {
            int rA = 2*q, rB = 2*q + 1;
            int gA = (r0t + rA) < w, gB = (r0t + rB) < w;
            float2 e0 = unpk(acc[q][0]);   // col c0,   rows (rA, rB)
            float2 e1 = unpk(acc[q][1]);   // col c0+1
            float2 n0 = unpk(acc[q][2]);
            float2 n1 = unpk(acc[q][3]);
            // pair_e col c0
            float p0A = e0.x + pfe[rA].x + be2v.x;
            float p0B = e0.y + pfe[rB].x + be2v.x;
            p0A = (gA && p0A > 0.f) ? p0A : 0.f;
            p0B = (gB && p0B > 0.f) ? p0B : 0.f;
            *(ull*)&sPeT[c0][r0t + rA] = pk(p0A, p0B);
            // pair_e col c0+1
            float p1A = e1.x + pfe[rA].y + be2v.y;
            float p1B = e1.y + pfe[rB].y + be2v.y;
            p1A = (gA && p1A > 0.f) ? p1A : 0.f;
            p1B = (gB && p1B > 0.f) ? p1B : 0.f;
            *(ull*)&sPeT[c0+1][r0t + rA] = pk(p1A, p1B);
            // pair_n col c0
            float q0A = n0.x + pfn[rA].x + pnd0.x + bn2v.x;
            float q0B = n0.y + pfn[rB].x + pnd0.x + bn2v.x;
            if (gA && q0A > 0.f) np0 += q0A;
            if (gB && q0B > 0.f) np0 += q0B;
            // pair_n col c0+1
            float q1A = n1.x + pfn[rA].y + pnd1.y + bn2v.y;
            float q1B = n1.y + pfn[rB].y + pnd1.y + bn2v.y;
            if (gA && q1A > 0.f) np1 += q1A;
            if (gB && q1B > 0.f) np1 += q1B;
        }
        *(ull*)&sred[ty][c0] = pk(np0, np1);
        __syncthreads();

        // agg_n write
        if (tid < 64) {
            float s = 0.f;
            #pragma unroll
            for (int t = 0; t < 8; t++) s += sred[t][tid];
            g_agg[(size_t)task*64 + tid] = s / (float)(w > 0 ? w : 1);
        }

        // ---- GEMM2: R = pair_e @ W_mean  (prefix commutes with GEMM) ----
        ull acc2[4][2];
        #pragma unroll
        for (int q = 0; q < 4; q++) { acc2[q][0] = 0ull; acc2[q][1] = 0ull; }
        #pragma unroll 8
        for (int j = 0; j < 64; j++) {
            ull a2[4];
            #pragma unroll
            for (int q = 0; q < 4; q++) a2[q] = *(const ull*)&sPeT[j][r0t + 2*q];
            float2 wp = *(const float2*)&sW2[j*64 + c0];
            ull w20 = bcast2(wp.x);
            ull w21 = bcast2(wp.y);
            #pragma unroll
            for (int q = 0; q < 4; q++) {
                fma2(acc2[q][0], a2[q], w20);
                fma2(acc2[q][1], a2[q], w21);
            }
        }

        // ---- exclusive row-prefix of R (in-register + warp carries) ----
        float s0[8], s1[8];
        #pragma unroll
        for (int q = 0; q < 4; q++) {
            float2 v0 = unpk(acc2[q][0]);
            float2 v1 = unpk(acc2[q][1]);
            s0[2*q] = v0.x; s0[2*q+1] = v0.y;
            s1[2*q] = v1.x; s1[2*q+1] = v1.y;
        }
        float ex0[8], ex1[8], run0 = 0.f, run1 = 0.f;
        #pragma unroll
        for (int ri = 0; ri < 8; ri++) {
            ex0[ri] = run0; run0 += s0[ri];
            ex1[ri] = run1; run1 += s1[ri];
        }
        swred[ty][tx] = pk(run0, run1);
        __syncthreads();
        float cc0 = 0.f, cc1 = 0.f;
        for (int t = 0; t < ty; t++) {
            float2 v = unpk(swred[t][tx]);
            cc0 += v.x; cc1 += v.y;
        }

        // ---- final: mean-scale + Q3 + bias, ReLU, float2 store ----
        float2 bo2v = *(const float2*)&sbo[c0];
        #pragma unroll
        for (int q = 0; q < 4; q++) {
            float2 t0 = unpk(acc[q][4]);   // Q3 col 128+c0, rows (rA,rB)
            float2 t1 = unpk(acc[q][5]);
            #pragma unroll
            for (int h = 0; h < 2; h++) {
                int ri = 2*q + h;
                int r  = r0t + ri;
                if (r < w) {
                    float rc = srcp[r];
                    size_t orow = (ebase + r)*64;
                    float v0 = (ex0[ri] + cc0)*rc + (h ? t0.y : t0.x) + bo2v.x;
                    float v1 = (ex1[ri] + cc1)*rc + (h ? t1.y : t1.x) + bo2v.y;
                    float2 o; o.x = v0 > 0.f ? v0 : 0.f; o.y = v1 > 0.f ? v1 : 0.f;
                    *(float2*)&out_edges[orow + c0] = o;
                }
            }
        }
    }
}

// ---------------- K3: out_nodes (NROWS x 128) @ (128 x 64) ----------------
__global__ void __launch_bounds__(256,2) k_outnodes(float* __restrict__ out,
                                                    const float* __restrict__ nodes,
                                                    const float* __restrict__ W_nodes,
                                                    const float* __restrict__ bias) {
    __shared__ float sW[128*64];
    __shared__ float sA[64][132];
    __shared__ float sb[64];
    for (int idx = threadIdx.x; idx < 128*64; idx += 256) sW[idx] = W_nodes[idx];
    if (threadIdx.x < 64) sb[threadIdx.x] = bias[threadIdx.x];
    int tx = threadIdx.x & 31, ty = threadIdx.x >> 5;
    int tile = blockIdx.x;
    {
        const float4* sa = (const float4*)(g_agg + (size_t)tile*64*64);
        const float4* sn = (const float4*)(nodes + (size_t)tile*64*64);
        for (int idx = threadIdx.x; idx < 64*16; idx += 256) {
            int r = idx >> 4, q = idx & 15;
            ((float4*)&sA[r][0])[q]  = sa[idx];
            ((float4*)&sA[r][64])[q] = sn[idx];
        }
    }
    __syncthreads();
    float acc[8][2];
    #pragma unroll
    for (int a = 0; a < 8; a++) { acc[a][0] = 0.f; acc[a][1] = 0.f; }
    for (int j = 0; j < 128; j += 4) {
        float4 av[8];
        #pragma unroll
        for (int ri = 0; ri < 8; ri++) av[ri] = *(const float4*)&sA[ty + 8*ri][j];
        #pragma unroll
        for (int jj = 0; jj < 4; jj++) {
            float w0 = sW[(j+jj)*64 + tx];
            float w1 = sW[(j+jj)*64 + tx + 32];
            #pragma unroll
            for (int ri = 0; ri < 8; ri++) {
                float a = (jj==0) ? av[ri].x : (jj==1) ? av[ri].y : (jj==2) ? av[ri].z : av[ri].w;
                acc[ri][0] += a * w0;
                acc[ri][1] += a * w1;
            }
        }
    }
    #pragma unroll
    for (int ri = 0; ri < 8; ri++) {
        size_t row = (size_t)tile*64 + ty + 8*ri;
        float v0 = acc[ri][0] + sb[tx];
        float v1 = acc[ri][1] + sb[tx+32];
        out[row*64 + tx]      = v0 > 0.f ? v0 : 0.f;
        out[row*64 + tx + 32] = v1 > 0.f ? v1 : 0.f;
    }
}

// ---------------- launch ----------------
extern "C" void kernel_launch(void* const* d_in, const int* in_sizes, int n_in,
                              void* d_out, int out_size) {
    const float* input_nodes = (const float*)d_in[0];
    const float* input_edges = (const float*)d_in[1];
    const float* Wn1 = (const float*)d_in[2];
    const float* bn1 = (const float*)d_in[3];
    const float* Wn2 = (const float*)d_in[4];
    const float* bn2 = (const float*)d_in[5];
    const float* We1 = (const float*)d_in[6];
    const float* be1 = (const float*)d_in[7];
    const float* We2 = (const float*)d_in[8];
    const float* be2 = (const float*)d_in[9];
    const float* W_nodes    = (const float*)d_in[10];
    const float* W_edges    = (const float*)d_in[11];
    const float* bias_edges = (const float*)d_in[12];

    float* out       = (float*)d_out;
    float* out_nodes = out;
    float* out_edges = out + (size_t)Bq*Nn*64;

    k_fuse<<<(128*64 + 192*64 + 128 + 255)/256, 256>>>(We1, We2, be1, be2, Wn1, bn1, Wn2, bn2);
    k_cat<<<(64*192 + 255)/256, 256>>>(W_edges);
    k_nodeproj<<<128, 256>>>(input_nodes);
    k_fusededge<<<296, 256>>>(input_edges, W_edges, bias_edges, out_edges);
    k_outnodes<<<128, 256>>>(out_nodes, input_nodes, W_nodes, bias_edges);
}

// round 5
// speedup vs baseline: 2.2260x; 1.1209x over previous
#include <cuda_runtime.h>

#define Bq 8
#define Nn 1024
#define Mw 64
#define Ee 63456
#define NROWS (Bq*Nn)          /* 8192 node rows */

#define GRID    152
#define NSTREAM (GRID*2)       /* 304 task streams */

typedef unsigned long long ull;

// ---------------- device scratch ----------------
__device__ float g_We[128*64];          // fused We1@We2
__device__ float g_Wn[192*64];          // fused Wn1@Wn2
__device__ float g_be[64];
__device__ float g_bn[64];
__device__ float g_Wcat[64*192];        // edge-side:  [We_edge | Wn_edge | W_e_edge]
__device__ float g_WcatP[64*192];       // node-side:  [We_src  | Wn_src  | Wn_dst ]
__device__ float g_P[NROWS*192];        // node projections [Pes | Pns | Pnd]
__device__ float g_agg[NROWS*64];       // agg_n

__device__ __forceinline__ int node_w(int i)      { return i < Mw ? i : Mw; }
__device__ __forceinline__ int node_start(int i)  { return i <= Mw ? (i*(i-1))/2 : 2016 + (i-Mw)*Mw; }

// ---------------- packed fp32x2 helpers ----------------
__device__ __forceinline__ void fma2(ull &d, ull a, ull b) {
    asm("fma.rn.f32x2 %0, %1, %2, %0;" : "+l"(d) : "l"(a), "l"(b));
}
__device__ __forceinline__ ull bcast2(float x) {
    ull r; asm("mov.b64 %0, {%1, %1};" : "=l"(r) : "f"(x)); return r;
}
__device__ __forceinline__ float2 unpk(ull v) {
    float2 r; asm("mov.b64 {%0, %1}, %2;" : "=f"(r.x), "=f"(r.y) : "l"(v)); return r;
}
__device__ __forceinline__ ull pk(float x, float y) {
    ull r; asm("mov.b64 %0, {%1, %2};" : "=l"(r) : "f"(x), "f"(y)); return r;
}
__device__ __forceinline__ void gbar(int id) {
    asm volatile("bar.sync %0, %1;" :: "r"(id), "r"(256) : "memory");
}

// ---------------- shared layout (floats) for k_fusededge ----------------
#define SZ_AT    (64*66)       /* 4224 */
#define OFF_W1   0             /* 12288 */
#define OFF_W2   12288         /* 4096  */
#define OFF_BE   16384
#define OFF_BN   16448
#define OFF_BO   16512
#define OFF_RCP  16576
#define OFF_SWR  16640         /* ull[2][8][32] = 1024 floats */
#define OFF_AT   17664         /* [2 grp][2 buf][4224] = 16896 */
#define OFF_PET  34560         /* [2][4224] = 8448 */
#define OFF_SRED 43008         /* [2][512] */
#define SMEM_FLOATS 44032
#define SMEM_BYTES  (SMEM_FLOATS*4)

// ---------------- K0: fuse the two (linear∘linear) MLPs ----------------
__global__ void k_fuse(const float* __restrict__ We1, const float* __restrict__ We2,
                       const float* __restrict__ be1, const float* __restrict__ be2,
                       const float* __restrict__ Wn1, const float* __restrict__ bn1,
                       const float* __restrict__ Wn2, const float* __restrict__ bn2) {
    int idx = blockIdx.x*blockDim.x + threadIdx.x;
    if (idx < 128*64) {
        int j = idx >> 6, c = idx & 63; float s = 0.f;
        for (int t = 0; t < 128; t++) s += We1[j*128+t]*We2[t*64+c];
        g_We[idx] = s;
    }
    int i2 = idx - 128*64;
    if (i2 >= 0 && i2 < 192*64) {
        int j = i2 >> 6, c = i2 & 63; float s = 0.f;
        for (int t = 0; t < 128; t++) s += Wn1[j*128+t]*Wn2[t*64+c];
        g_Wn[i2] = s;
    }
    int i3 = idx - 128*64 - 192*64;
    if (i3 >= 0 && i3 < 64) {
        float s = be2[i3];
        for (int t = 0; t < 128; t++) s += be1[t]*We2[t*64+i3];
        g_be[i3] = s;
    }
    if (i3 >= 64 && i3 < 128) {
        int c = i3 - 64; float s = bn2[c];
        for (int t = 0; t < 128; t++) s += bn1[t]*Wn2[t*64+c];
        g_bn[c] = s;
    }
}

// ---------------- K0b: pack concatenated weight blocks ----------------
__global__ void k_cat(const float* __restrict__ W_edges) {
    int idx = blockIdx.x*blockDim.x + threadIdx.x;
    if (idx >= 64*192) return;
    int j = idx / 192, c = idx % 192;
    float ve, vp;
    if (c < 64)       { ve = g_We[(64+j)*64 + c];          vp = g_We[j*64 + c]; }
    else if (c < 128) { ve = g_Wn[(128+j)*64 + (c-64)];    vp = g_Wn[j*64 + (c-64)]; }
    else              { ve = W_edges[(64+j)*64 + (c-128)]; vp = g_Wn[(64+j)*64 + (c-128)]; }
    g_Wcat[idx]  = ve;
    g_WcatP[idx] = vp;
}

// ---------------- K1: node projections GEMM (NROWS x 64) @ (64 x 192) ----------------
__global__ void __launch_bounds__(256,2) k_nodeproj(const float* __restrict__ A) {
    __shared__ float sW[64*192];
    __shared__ float sA[64][68];
    for (int idx = threadIdx.x; idx < 64*192; idx += 256) sW[idx] = g_WcatP[idx];
    int tx = threadIdx.x & 31, ty = threadIdx.x >> 5;
    const int NT = NROWS/64;
    for (int tile = blockIdx.x; tile < NT; tile += gridDim.x) {
        __syncthreads();
        const float4* src = (const float4*)(A + (size_t)tile*64*64);
        for (int idx = threadIdx.x; idx < 64*16; idx += 256) {
            int r = idx >> 4, q = idx & 15;
            ((float4*)&sA[r][0])[q] = src[idx];
        }
        __syncthreads();
        float acc[8][6];
        #pragma unroll
        for (int a = 0; a < 8; a++)
            #pragma unroll
            for (int b = 0; b < 6; b++) acc[a][b] = 0.f;
        for (int j = 0; j < 64; j += 4) {
            float4 av[8];
            #pragma unroll
            for (int ri = 0; ri < 8; ri++) av[ri] = *(const float4*)&sA[ty + 8*ri][j];
            #pragma unroll
            for (int jj = 0; jj < 4; jj++) {
                float wv[6];
                #pragma unroll
                for (int ci = 0; ci < 6; ci++) wv[ci] = sW[(j+jj)*192 + tx + 32*ci];
                #pragma unroll
                for (int ri = 0; ri < 8; ri++) {
                    float a = (jj==0) ? av[ri].x : (jj==1) ? av[ri].y : (jj==2) ? av[ri].z : av[ri].w;
                    #pragma unroll
                    for (int ci = 0; ci < 6; ci++) acc[ri][ci] += a * wv[ci];
                }
            }
        }
        float* dst = g_P + (size_t)tile*64*192;
        #pragma unroll
        for (int ri = 0; ri < 8; ri++) {
            int r = ty + 8*ri;
            #pragma unroll
            for (int ci = 0; ci < 6; ci++)
                dst[(size_t)r*192 + tx + 32*ci] = acc[ri][ci];
        }
    }
}

// ---------------- K2: fused per-node pipeline; 2 warp-groups/CTA; double-buffered tiles ----------------
__global__ void __launch_bounds__(512,1) k_fusededge(const float* __restrict__ edges,
                                                     const float* __restrict__ W_edges,
                                                     const float* __restrict__ bias,
                                                     float* __restrict__ out_edges) {
    extern __shared__ float sm[];
    float* sW1  = sm + OFF_W1;
    float* sW2  = sm + OFF_W2;
    float* sbe  = sm + OFF_BE;
    float* sbn  = sm + OFF_BN;
    float* sbo  = sm + OFF_BO;
    float* srcp = sm + OFF_RCP;
    int tid = threadIdx.x;

    for (int idx = tid; idx < 64*192; idx += 512) sW1[idx] = g_Wcat[idx];
    for (int idx = tid; idx < 64*64;  idx += 512) sW2[idx] = W_edges[idx];
    if (tid < 64) {
        sbe[tid] = g_be[tid];
        sbn[tid] = g_bn[tid];
        sbo[tid] = bias[tid];
        srcp[tid] = 1.0f / (float)(tid > 0 ? tid : 1);
    }
    __syncthreads();

    int grp  = tid >> 8;            // warp-group 0/1
    int gtid = tid & 255;
    int tx = gtid & 31, gty = gtid >> 5;
    int r0t = 8*gty;                // group-warp's first row
    int c0  = 2*tx;                 // first col in each 64-group
    int bar = grp + 1;

    ull*   swred = (ull*)(sm + OFF_SWR) + grp*(8*32);
    float* sPeT  = sm + OFF_PET  + grp*SZ_AT;
    float* sred  = sm + OFF_SRED + grp*512;
    float* bufA  = sm + OFF_AT + (grp*2+0)*SZ_AT;
    float* bufB  = sm + OFF_AT + (grp*2+1)*SZ_AT;

    int task = blockIdx.x*2 + grp;          // stream id; step NSTREAM

    // ---- prologue: load first tile into bufA (full 64 rows, always in-bounds) ----
    {
        int b = task >> 10, i = task & 1023;
        size_t ebase = (size_t)b*Ee + node_start(i);
        const float4* src = (const float4*)(edges + ebase*64);
        #pragma unroll
        for (int k = 0; k < 4; k++) {
            int idx = gtid + 256*k;
            float4 v = __ldg(src + idx);
            int r = idx >> 4, j = 4*(idx & 15);
            bufA[(j+0)*66 + r] = v.x; bufA[(j+1)*66 + r] = v.y;
            bufA[(j+2)*66 + r] = v.z; bufA[(j+3)*66 + r] = v.w;
        }
    }
    gbar(bar);

    float* curAT = bufA;
    float* nxtAT = bufB;

    for (; task < Bq*Nn; task += NSTREAM) {
        int b = task >> 10, i = task & 1023;
        int w = node_w(i), ns = node_start(i);
        size_t ebase = (size_t)b*Ee + ns;
        int srow0 = (b << 10) + (i - w);
        int ntask = task + NSTREAM;
        bool hasn = ntask < Bq*Nn;

        // ---- GEMM1: Q = A @ Wcat (row-pair f32x2, col-pair W) ----
        ull acc[4][6];
        #pragma unroll
        for (int q = 0; q < 4; q++)
            #pragma unroll
            for (int c2 = 0; c2 < 6; c2++) acc[q][c2] = 0ull;
        #pragma unroll 8
        for (int j = 0; j < 64; j++) {
            ull a2[4];
            #pragma unroll
            for (int q = 0; q < 4; q++) a2[q] = *(const ull*)&curAT[j*66 + r0t + 2*q];
            #pragma unroll
            for (int g = 0; g < 3; g++) {
                float2 wp = *(const float2*)&sW1[j*192 + 64*g + c0];
                ull w20 = bcast2(wp.x);
                ull w21 = bcast2(wp.y);
                #pragma unroll
                for (int q = 0; q < 4; q++) {
                    fma2(acc[q][2*g+0], a2[q], w20);
                    fma2(acc[q][2*g+1], a2[q], w21);
                }
            }
        }

        // ---- per-row node projections (float2 over col pair) ----
        float2 pnd, pfe[8], pfn[8];
        {
            size_t pb = (size_t)task*192;
            pnd = *(const float2*)&g_P[pb + 128 + c0];
            #pragma unroll
            for (int ri = 0; ri < 8; ri++) {
                size_t sr = (size_t)(srow0 + r0t + ri)*192;
                pfe[ri] = *(const float2*)&g_P[sr + c0];
                pfn[ri] = *(const float2*)&g_P[sr + 64 + c0];
            }
        }
        float2 be2v = *(const float2*)&sbe[c0];
        float2 bn2v = *(const float2*)&sbn[c0];

        // ---- epilogue: ReLU; pair_e -> sPeT (row-pair STS.64); pair_n col sums ----
        float np0 = 0.f, np1 = 0.f;
        #pragma unroll
        for (int q = 0; q < 4; q++) {
            int rA = 2*q, rB = 2*q + 1;
            int gA = (r0t + rA) < w, gB = (r0t + rB) < w;
            float2 e0 = unpk(acc[q][0]);
            float2 e1 = unpk(acc[q][1]);
            float2 n0 = unpk(acc[q][2]);
            float2 n1 = unpk(acc[q][3]);
            float p0A = e0.x + pfe[rA].x + be2v.x;
            float p0B = e0.y + pfe[rB].x + be2v.x;
            p0A = (gA && p0A > 0.f) ? p0A : 0.f;
            p0B = (gB && p0B > 0.f) ? p0B : 0.f;
            *(ull*)&sPeT[c0*66 + r0t + rA] = pk(p0A, p0B);
            float p1A = e1.x + pfe[rA].y + be2v.y;
            float p1B = e1.y + pfe[rB].y + be2v.y;
            p1A = (gA && p1A > 0.f) ? p1A : 0.f;
            p1B = (gB && p1B > 0.f) ? p1B : 0.f;
            *(ull*)&sPeT[(c0+1)*66 + r0t + rA] = pk(p1A, p1B);
            float q0A = n0.x + pfn[rA].x + pnd.x + bn2v.x;
            float q0B = n0.y + pfn[rB].x + pnd.x + bn2v.x;
            if (gA && q0A > 0.f) np0 += q0A;
            if (gB && q0B > 0.f) np0 += q0B;
            float q1A = n1.x + pfn[rA].y + pnd.y + bn2v.y;
            float q1B = n1.y + pfn[rB].y + pnd.y + bn2v.y;
            if (gA && q1A > 0.f) np1 += q1A;
            if (gB && q1B > 0.f) np1 += q1B;
        }
        *(ull*)&sred[gty*64 + c0] = pk(np0, np1);

        // ---- issue prefetch LDGs for next tile (in flight under GEMM2) ----
        float4 pf4[4];
        if (hasn) {
            int nb = ntask >> 10, ni = ntask & 1023;
            size_t nebase = (size_t)nb*Ee + node_start(ni);
            const float4* nsrc = (const float4*)(edges + nebase*64);
            #pragma unroll
            for (int k = 0; k < 4; k++) pf4[k] = __ldg(nsrc + gtid + 256*k);
        }
        gbar(bar);                               // B1: sPeT/sred ready

        // agg_n write
        if (gtid < 64) {
            float s = 0.f;
            #pragma unroll
            for (int t = 0; t < 8; t++) s += sred[t*64 + gtid];
            g_agg[(size_t)task*64 + gtid] = s / (float)(w > 0 ? w : 1);
        }

        // ---- GEMM2: R = pair_e @ W_mean (prefix commutes with GEMM) ----
        ull acc2[4][2];
        #pragma unroll
        for (int q = 0; q < 4; q++) { acc2[q][0] = 0ull; acc2[q][1] = 0ull; }
        #pragma unroll 8
        for (int j = 0; j < 64; j++) {
            ull a2[4];
            #pragma unroll
            for (int q = 0; q < 4; q++) a2[q] = *(const ull*)&sPeT[j*66 + r0t + 2*q];
            float2 wp = *(const float2*)&sW2[j*64 + c0];
            ull w20 = bcast2(wp.x);
            ull w21 = bcast2(wp.y);
            #pragma unroll
            for (int q = 0; q < 4; q++) {
                fma2(acc2[q][0], a2[q], w20);
                fma2(acc2[q][1], a2[q], w21);
            }
        }

        // ---- exclusive row-prefix (in-register) + warp totals ----
        float s0[8], s1[8];
        #pragma unroll
        for (int q = 0; q < 4; q++) {
            float2 v0 = unpk(acc2[q][0]);
            float2 v1 = unpk(acc2[q][1]);
            s0[2*q] = v0.x; s0[2*q+1] = v0.y;
            s1[2*q] = v1.x; s1[2*q+1] = v1.y;
        }
        float ex0[8], ex1[8], run0 = 0.f, run1 = 0.f;
        #pragma unroll
        for (int ri = 0; ri < 8; ri++) {
            ex0[ri] = run0; run0 += s0[ri];
            ex1[ri] = run1; run1 += s1[ri];
        }
        swred[gty*32 + tx] = pk(run0, run1);

        // ---- store prefetched tile into alternate buffer ----
        if (hasn) {
            #pragma unroll
            for (int k = 0; k < 4; k++) {
                int idx = gtid + 256*k;
                int r = idx >> 4, j = 4*(idx & 15);
                nxtAT[(j+0)*66 + r] = pf4[k].x; nxtAT[(j+1)*66 + r] = pf4[k].y;
                nxtAT[(j+2)*66 + r] = pf4[k].z; nxtAT[(j+3)*66 + r] = pf4[k].w;
            }
        }
        gbar(bar);                               // B2: swred + next tile ready

        // ---- warp-carry (predicated, unrolled) ----
        float cc0 = 0.f, cc1 = 0.f;
        #pragma unroll
        for (int t = 0; t < 7; t++) {
            if (t < gty) {
                float2 v = unpk(swred[t*32 + tx]);
                cc0 += v.x; cc1 += v.y;
            }
        }

        // ---- final: mean-scale + Q3 + bias, ReLU, float2 store ----
        float2 bo2v = *(const float2*)&sbo[c0];
        #pragma unroll
        for (int q = 0; q < 4; q++) {
            float2 t0 = unpk(acc[q][4]);
            float2 t1 = unpk(acc[q][5]);
            #pragma unroll
            for (int h = 0; h < 2; h++) {
                int ri = 2*q + h;
                int r  = r0t + ri;
                if (r < w) {
                    float rc = srcp[r];
                    size_t orow = (ebase + r)*64;
                    float v0 = (ex0[ri] + cc0)*rc + (h ? t0.y : t0.x) + bo2v.x;
                    float v1 = (ex1[ri] + cc1)*rc + (h ? t1.y : t1.x) + bo2v.y;
                    float2 o; o.x = v0 > 0.f ? v0 : 0.f; o.y = v1 > 0.f ? v1 : 0.f;
                    *(float2*)&out_edges[orow + c0] = o;
                }
            }
        }

        float* t = curAT; curAT = nxtAT; nxtAT = t;
    }
}

// ---------------- K3: out_nodes (NROWS x 128) @ (128 x 64) ----------------
__global__ void __launch_bounds__(256,2) k_outnodes(float* __restrict__ out,
                                                    const float* __restrict__ nodes,
                                                    const float* __restrict__ W_nodes,
                                                    const float* __restrict__ bias) {
    __shared__ float sW[128*64];
    __shared__ float sA[64][132];
    __shared__ float sb[64];
    for (int idx = threadIdx.x; idx < 128*64; idx += 256) sW[idx] = W_nodes[idx];
    if (threadIdx.x < 64) sb[threadIdx.x] = bias[threadIdx.x];
    int tx = threadIdx.x & 31, ty = threadIdx.x >> 5;
    int tile = blockIdx.x;
    {
        const float4* sa = (const float4*)(g_agg + (size_t)tile*64*64);
        const float4* sn = (const float4*)(nodes + (size_t)tile*64*64);
        for (int idx = threadIdx.x; idx < 64*16; idx += 256) {
            int r = idx >> 4, q = idx & 15;
            ((float4*)&sA[r][0])[q]  = sa[idx];
            ((float4*)&sA[r][64])[q] = sn[idx];
        }
    }
    __syncthreads();
    float acc[8][2];
    #pragma unroll
    for (int a = 0; a < 8; a++) { acc[a][0] = 0.f; acc[a][1] = 0.f; }
    for (int j = 0; j < 128; j += 4) {
        float4 av[8];
        #pragma unroll
        for (int ri = 0; ri < 8; ri++) av[ri] = *(const float4*)&sA[ty + 8*ri][j];
        #pragma unroll
        for (int jj = 0; jj < 4; jj++) {
            float w0 = sW[(j+jj)*64 + tx];
            float w1 = sW[(j+jj)*64 + tx + 32];
            #pragma unroll
            for (int ri = 0; ri < 8; ri++) {
                float a = (jj==0) ? av[ri].x : (jj==1) ? av[ri].y : (jj==2) ? av[ri].z : av[ri].w;
                acc[ri][0] += a * w0;
                acc[ri][1] += a * w1;
            }
        }
    }
    #pragma unroll
    for (int ri = 0; ri < 8; ri++) {
        size_t row = (size_t)tile*64 + ty + 8*ri;
        float v0 = acc[ri][0] + sb[tx];
        float v1 = acc[ri][1] + sb[tx+32];
        out[row*64 + tx]      = v0 > 0.f ? v0 : 0.f;
        out[row*64 + tx + 32] = v1 > 0.f ? v1 : 0.f;
    }
}

// ---------------- launch ----------------
extern "C" void kernel_launch(void* const* d_in, const int* in_sizes, int n_in,
                              void* d_out, int out_size) {
    const float* input_nodes = (const float*)d_in[0];
    const float* input_edges = (const float*)d_in[1];
    const float* Wn1 = (const float*)d_in[2];
    const float* bn1 = (const float*)d_in[3];
    const float* Wn2 = (const float*)d_in[4];
    const float* bn2 = (const float*)d_in[5];
    const float* We1 = (const float*)d_in[6];
    const float* be1 = (const float*)d_in[7];
    const float* We2 = (const float*)d_in[8];
    const float* be2 = (const float*)d_in[9];
    const float* W_nodes    = (const float*)d_in[10];
    const float* W_edges    = (const float*)d_in[11];
    const float* bias_edges = (const float*)d_in[12];

    float* out       = (float*)d_out;
    float* out_nodes = out;
    float* out_edges = out + (size_t)Bq*Nn*64;

    cudaFuncSetAttribute(k_fusededge, cudaFuncAttributeMaxDynamicSharedMemorySize, SMEM_BYTES);

    k_fuse<<<(128*64 + 192*64 + 128 + 255)/256, 256>>>(We1, We2, be1, be2, Wn1, bn1, Wn2, bn2);
    k_cat<<<(64*192 + 255)/256, 256>>>(W_edges);
    k_nodeproj<<<128, 256>>>(input_nodes);
    k_fusededge<<<GRID, 512, SMEM_BYTES>>>(input_edges, W_edges, bias_edges, out_edges);
    k_outnodes<<<128, 256>>>(out_nodes, input_nodes, W_nodes, bias_edges);
}